// round 1
// baseline (speedup 1.0000x reference)
#include <cuda_runtime.h>

#define NL 50
#define THREADS 256

// Per-block: one batch row. Streams (z, val) pairs, maps z -> bin weight,
// accumulates val * w(bin), block-reduces, adds dot(bias, weight).
__global__ __launch_bounds__(THREADS) void zws_kernel(
    const float4* __restrict__ x,      // (B, V/2) float4 = 2 (z,val) pairs each
    const float*  __restrict__ weight, // (NL,)
    const float*  __restrict__ bias,   // (NL,)
    float*        __restrict__ out,    // (B,)
    int nf4_per_row)                   // V/2
{
    // +2 padding: sentinel slots at [0] and [NL+1] so candidate-1/+1 checks
    // need no bounds test (sentinels can never satisfy lo < z < hi).
    __shared__ float lo_s[NL + 2];
    __shared__ float hi_s[NL + 2];
    __shared__ float w_s[NL];

    const int tid = threadIdx.x;

    float acc = 0.0f;

    if (tid < NL) {
        // Reproduce numpy edge construction bit-exactly:
        //   low  = concat(arange(0,25,1),  arange(25,200,7)) / 200.0 * (120.0/200.0)  -> f32
        //   high = concat(arange(1,26,1),  arange(32,207,7)) / 200.0 * (120.0/200.0)  -> f32
        double lo_d = (tid < 25 ? (double)tid        : 25.0 + 7.0 * (tid - 25));
        double hi_d = (tid < 25 ? (double)(tid + 1)  : 32.0 + 7.0 * (tid - 25));
        lo_s[tid + 1] = (float)(lo_d / 200.0 * 0.6);
        hi_s[tid + 1] = (float)(hi_d / 200.0 * 0.6);
        float w = weight[tid];
        w_s[tid] = w;
        // Fold dot(bias, weight) into the reduction (once per block).
        acc = bias[tid] * w;
    }
    if (tid == 0) {
        lo_s[0]      = 3.0e38f;  hi_s[0]      = -3.0e38f;
        lo_s[NL + 1] = 3.0e38f;  hi_s[NL + 1] = -3.0e38f;
    }
    __syncthreads();

    const float4* row = x + (size_t)blockIdx.x * nf4_per_row;

    // Each float4 = two (z, val) pairs. 256 threads stride the row.
    #pragma unroll 8
    for (int i = tid; i < nf4_per_row; i += THREADS) {
        float4 p = __ldg(&row[i]);

        // pair 0: (p.x = z, p.y = val)
        {
            float z = p.x;
            float t = z * (200.0f / 0.6f);
            int c = (t < 25.0f) ? (int)t : 25 + (int)((t - 25.0f) * (1.0f / 7.0f));
            c = min(max(c, 0), NL - 1);
            float w = 0.0f;
            #pragma unroll
            for (int d = -1; d <= 1; ++d) {
                int j = c + d;                    // j in [-1, NL] -> shifted idx in [0, NL+1]
                if (z > lo_s[j + 1] && z < hi_s[j + 1]) w = w_s[j];
            }
            acc = fmaf(p.y, w, acc);
        }
        // pair 1: (p.z = z, p.w = val)
        {
            float z = p.z;
            float t = z * (200.0f / 0.6f);
            int c = (t < 25.0f) ? (int)t : 25 + (int)((t - 25.0f) * (1.0f / 7.0f));
            c = min(max(c, 0), NL - 1);
            float w = 0.0f;
            #pragma unroll
            for (int d = -1; d <= 1; ++d) {
                int j = c + d;
                if (z > lo_s[j + 1] && z < hi_s[j + 1]) w = w_s[j];
            }
            acc = fmaf(p.w, w, acc);
        }
    }

    // Warp reduction
    #pragma unroll
    for (int o = 16; o; o >>= 1)
        acc += __shfl_down_sync(0xFFFFFFFFu, acc, o);

    __shared__ float red[THREADS / 32];
    if ((tid & 31) == 0) red[tid >> 5] = acc;
    __syncthreads();

    if (tid < THREADS / 32) {
        float s = red[tid];
        #pragma unroll
        for (int o = (THREADS / 64); o; o >>= 1)
            s += __shfl_down_sync(0xFFu, s, o);
        if (tid == 0) out[blockIdx.x] = s;
    }
}

extern "C" void kernel_launch(void* const* d_in, const int* in_sizes, int n_in,
                              void* d_out, int out_size)
{
    const float4* x      = (const float4*)d_in[0];  // (B, V, 2) float32
    const float*  weight = (const float*)d_in[1];   // (NL, 1)
    const float*  bias   = (const float*)d_in[2];   // (NL,)
    float*        out    = (float*)d_out;           // (B,)

    const int B = out_size;                          // 256
    const int pairs_total = in_sizes[0] / 2;         // B * V
    const int nf4_per_row = pairs_total / B / 2;     // V / 2 = 2048

    zws_kernel<<<B, THREADS>>>(x, weight, bias, out, nf4_per_row);
}